// round 2
// baseline (speedup 1.0000x reference)
#include <cuda_runtime.h>
#include <cuda_bf16.h>

// Triplet margin loss, D=4096 fp32, B=24576 rows -> 8192 triplets.
// Pure HBM-streaming problem: read 402.7 MB once, emit one scalar.

#define MARGIN 1.0f
#define D_DIM  4096
#define D4     (D_DIM / 4)   // 1024 float4 per row
#define NTHREADS 256

__device__ float g_loss_sum;

__global__ void tl_init_kernel() {
    g_loss_sum = 0.0f;
}

__global__ __launch_bounds__(NTHREADS) void tl_main_kernel(const float4* __restrict__ x) {
    const int t = blockIdx.x;                       // triplet index
    const float4* __restrict__ q = x + (size_t)t * 3 * D4;
    const float4* __restrict__ p = q + D4;
    const float4* __restrict__ n = p + D4;

    float sqp = 0.0f;   // sum (q-p)^2
    float sqn = 0.0f;   // sum (q-n)^2

    // 1024 float4 per row / 256 threads = 4 iterations; unrolled so ptxas
    // front-batches 12 independent LDG.128s (high MLP hides DRAM latency).
    #pragma unroll
    for (int it = 0; it < D4 / NTHREADS; ++it) {
        const int i = it * NTHREADS + threadIdx.x;
        const float4 qa = q[i];
        const float4 pa = p[i];
        const float4 na = n[i];
        float d;
        d = qa.x - pa.x; sqp = fmaf(d, d, sqp);
        d = qa.y - pa.y; sqp = fmaf(d, d, sqp);
        d = qa.z - pa.z; sqp = fmaf(d, d, sqp);
        d = qa.w - pa.w; sqp = fmaf(d, d, sqp);
        d = qa.x - na.x; sqn = fmaf(d, d, sqn);
        d = qa.y - na.y; sqn = fmaf(d, d, sqn);
        d = qa.z - na.z; sqn = fmaf(d, d, sqn);
        d = qa.w - na.w; sqn = fmaf(d, d, sqn);
    }

    // Warp reduction of the pair
    #pragma unroll
    for (int off = 16; off > 0; off >>= 1) {
        sqp += __shfl_down_sync(0xFFFFFFFFu, sqp, off);
        sqn += __shfl_down_sync(0xFFFFFFFFu, sqn, off);
    }

    __shared__ float s_qp[NTHREADS / 32];
    __shared__ float s_qn[NTHREADS / 32];
    const int lane = threadIdx.x & 31;
    const int wid  = threadIdx.x >> 5;
    if (lane == 0) { s_qp[wid] = sqp; s_qn[wid] = sqn; }
    __syncthreads();

    if (wid == 0) {
        sqp = (lane < NTHREADS / 32) ? s_qp[lane] : 0.0f;
        sqn = (lane < NTHREADS / 32) ? s_qn[lane] : 0.0f;
        #pragma unroll
        for (int off = 4; off > 0; off >>= 1) {
            sqp += __shfl_down_sync(0xFFFFFFFFu, sqp, off);
            sqn += __shfl_down_sync(0xFFFFFFFFu, sqn, off);
        }
        if (lane == 0) {
            const float hinge = MARGIN + sqrtf(sqp) - sqrtf(sqn);
            if (hinge > 0.0f) atomicAdd(&g_loss_sum, hinge);
        }
    }
}

__global__ void tl_final_kernel(float* __restrict__ out, float inv_triplets) {
    const float s = g_loss_sum * inv_triplets;
    out[0] = fmaxf(s, 0.0f);
}

extern "C" void kernel_launch(void* const* d_in, const int* in_sizes, int n_in,
                              void* d_out, int out_size) {
    const float4* x = (const float4*)d_in[0];
    float* out = (float*)d_out;

    const long long total = in_sizes[0];         // B * D
    const int triplets = (int)(total / (3LL * D_DIM));

    tl_init_kernel<<<1, 1>>>();
    tl_main_kernel<<<triplets, NTHREADS>>>(x);
    tl_final_kernel<<<1, 1>>>(out, 1.0f / (float)triplets);
}

// round 5
// speedup vs baseline: 1.0143x; 1.0143x over previous
#include <cuda_runtime.h>
#include <cuda_bf16.h>

// Triplet margin loss, D=4096 fp32, B=24576 rows -> 8192 triplets.
// Pure HBM-streaming problem: read 402.7 MB once, emit one scalar.
// Single persistent-fence kernel: last CTA to finish does the finalize and
// resets the device-global accumulators, so no init/final launches are needed
// and the zero-state invariant holds across graph replays.

#define MARGIN 1.0f
#define D_DIM  4096
#define D4     (D_DIM / 4)   // 1024 float4 per row
#define NTHREADS 256

__device__ float        g_loss_sum  = 0.0f;
__device__ unsigned int g_done_ctas = 0u;

__global__ __launch_bounds__(NTHREADS) void tl_fused_kernel(
    const float4* __restrict__ x, float* __restrict__ out,
    int triplets, float inv_triplets)
{
    const int t = blockIdx.x;                       // triplet index
    const float4* __restrict__ q = x + (size_t)t * 3 * D4;
    const float4* __restrict__ p = q + D4;
    const float4* __restrict__ n = p + D4;

    float sqp = 0.0f;   // sum (q-p)^2
    float sqn = 0.0f;   // sum (q-n)^2

    // 1024 float4 per row / 256 threads = 4 iterations; fully unrolled so
    // ptxas front-batches 12 independent LDG.128s (MLP hides DRAM latency).
    #pragma unroll
    for (int it = 0; it < D4 / NTHREADS; ++it) {
        const int i = it * NTHREADS + threadIdx.x;
        const float4 qa = q[i];
        const float4 pa = p[i];
        const float4 na = n[i];
        float d;
        d = qa.x - pa.x; sqp = fmaf(d, d, sqp);
        d = qa.y - pa.y; sqp = fmaf(d, d, sqp);
        d = qa.z - pa.z; sqp = fmaf(d, d, sqp);
        d = qa.w - pa.w; sqp = fmaf(d, d, sqp);
        d = qa.x - na.x; sqn = fmaf(d, d, sqn);
        d = qa.y - na.y; sqn = fmaf(d, d, sqn);
        d = qa.z - na.z; sqn = fmaf(d, d, sqn);
        d = qa.w - na.w; sqn = fmaf(d, d, sqn);
    }

    // Warp reduction of the pair
    #pragma unroll
    for (int off = 16; off > 0; off >>= 1) {
        sqp += __shfl_down_sync(0xFFFFFFFFu, sqp, off);
        sqn += __shfl_down_sync(0xFFFFFFFFu, sqn, off);
    }

    __shared__ float s_qp[NTHREADS / 32];
    __shared__ float s_qn[NTHREADS / 32];
    const int lane = threadIdx.x & 31;
    const int wid  = threadIdx.x >> 5;
    if (lane == 0) { s_qp[wid] = sqp; s_qn[wid] = sqn; }
    __syncthreads();

    if (wid == 0 && lane == 0) {
        float a = 0.0f, b = 0.0f;
        #pragma unroll
        for (int w = 0; w < NTHREADS / 32; ++w) { a += s_qp[w]; b += s_qn[w]; }
        const float hinge = MARGIN + sqrtf(a) - sqrtf(b);
        if (hinge > 0.0f) atomicAdd(&g_loss_sum, hinge);

        // Make this CTA's contribution globally visible, then arrive.
        __threadfence();
        const unsigned int old = atomicAdd(&g_done_ctas, 1u);
        if (old == (unsigned int)triplets - 1u) {
            // Last CTA: all adds are visible (fence-before-arrive on every
            // CTA). Read via atomic to bypass non-coherent L1.
            const float s = atomicAdd(&g_loss_sum, 0.0f);
            out[0] = fmaxf(s * inv_triplets, 0.0f);
            // Reset state for the next graph replay (atomicExch -> L2-resident,
            // no L1 writeback ambiguity for the next replay's first atomic).
            atomicExch(&g_loss_sum, 0.0f);
            __threadfence();
            atomicExch(&g_done_ctas, 0u);
        }
    }
}

extern "C" void kernel_launch(void* const* d_in, const int* in_sizes, int n_in,
                              void* d_out, int out_size) {
    const float4* x = (const float4*)d_in[0];
    float* out = (float*)d_out;

    const long long total = in_sizes[0];         // B * D
    const int triplets = (int)(total / (3LL * D_DIM));

    tl_fused_kernel<<<triplets, NTHREADS>>>(x, out, triplets, 1.0f / (float)triplets);
}